// round 7
// baseline (speedup 1.0000x reference)
#include <cuda_runtime.h>

#define NOUT 48
#define WPAD 56          // ws row stride: tg*56 mod 32 = {0,24,16,8} -> conflict-free LDS
#define CIN 384
#define NPIX 35200       // 200*176, multiple of 32
#define NB 4
#define TOTAL_PIX 140800 // = 550 * 256

extern __shared__ float s_buf[];   // ws[CIN][WPAD] (tf32-rounded), then bs[48]

__device__ __forceinline__ float to_tf32(float x) {
    float r;
    asm("cvt.rna.tf32.f32 %0, %1;" : "=f"(r) : "f"(x));
    return r;
}

// D (=C in-place) 16x8 fp32 += A(16x8 tf32, row) * B(8x8 tf32, col)
__device__ __forceinline__ void mma_tf32(float c[4], const unsigned a[4], const unsigned b[2]) {
    asm("mma.sync.aligned.m16n8k8.row.col.f32.tf32.tf32.f32 "
        "{%0,%1,%2,%3}, {%4,%5,%6,%7}, {%8,%9}, {%0,%1,%2,%3};"
        : "+f"(c[0]), "+f"(c[1]), "+f"(c[2]), "+f"(c[3])
        : "r"(a[0]), "r"(a[1]), "r"(a[2]), "r"(a[3]), "r"(b[0]), "r"(b[1]));
}

__global__ __launch_bounds__(256, 2)
void proposal_kernel(const float* __restrict__ feat,
                     const float* __restrict__ Wc,
                     const float* __restrict__ bc,
                     const float* __restrict__ Wr,
                     const float* __restrict__ br,
                     float* __restrict__ out)
{
    float* ws = s_buf;                   // ws[c*WPAD + o] = tf32(W[o][c])
    float* bs = s_buf + CIN * WPAD;

    const int tid = threadIdx.x;

    for (int i = tid; i < CIN * NOUT; i += blockDim.x) {
        const int c = i / NOUT;
        const int o = i % NOUT;
        ws[c * WPAD + o] = to_tf32((o < 6) ? Wc[o * CIN + c] : Wr[(o - 6) * CIN + c]);
    }
    if (tid < NOUT) bs[tid] = (tid < 6) ? bc[tid] : br[tid - 6];
    __syncthreads();

    const int lane = tid & 31;
    const int warp = tid >> 5;           // 8 warps; warp owns 32 consecutive pixels
    const int gid  = lane >> 2;          // 0..7
    const int tg   = lane & 3;           // 0..3

    // pixel bijection: fragment row (mt, h, gid) -> px = pbase + 2*(h*8+gid) + mt
    // => one float2 load feeds the same a-reg of BOTH m-tiles (.x->mt0, .y->mt1)
    const int m_base = blockIdx.x * 256 + warp * 32;   // 32-px window, single batch
    const int b      = m_base / NPIX;
    const int pbase  = m_base % NPIX;
    const int pH0    = pbase + 2 * gid;        // h=0 pair base (even)
    const int pH1    = pH0 + 16;               // h=1 pair base

    const float* fptr = feat + (long)b * CIN * NPIX;

    // acc[mt][nt][0..3]: c0=(h0, col even) c1=(h0, odd) c2=(h1, even) c3=(h1, odd)
    // columns: n = 8*nt + 2*tg (+1)
    float acc[2][6][4];
#pragma unroll
    for (int mt = 0; mt < 2; mt++)
#pragma unroll
        for (int nt = 0; nt < 6; nt++) {
            const float be = bs[8 * nt + 2 * tg];
            const float bo = bs[8 * nt + 2 * tg + 1];
            acc[mt][nt][0] = be; acc[mt][nt][1] = bo;
            acc[mt][nt][2] = be; acc[mt][nt][3] = bo;
        }

    const unsigned* wsu = (const unsigned*)ws;

#pragma unroll 2
    for (int k0 = 0; k0 < CIN; k0 += 8) {
        const float* c0 = fptr + (long)(k0 + tg)     * NPIX;
        const float* c1 = fptr + (long)(k0 + tg + 4) * NPIX;
        const float2 L00 = *(const float2*)(c0 + pH0);   // (h0, k=tg)   .x=mt0 .y=mt1
        const float2 L10 = *(const float2*)(c0 + pH1);   // (h1, k=tg)
        const float2 L01 = *(const float2*)(c1 + pH0);   // (h0, k=tg+4)
        const float2 L11 = *(const float2*)(c1 + pH1);   // (h1, k=tg+4)

        unsigned a0[4], a1[4];
        a0[0] = __float_as_uint(to_tf32(L00.x));
        a0[1] = __float_as_uint(to_tf32(L10.x));
        a0[2] = __float_as_uint(to_tf32(L01.x));
        a0[3] = __float_as_uint(to_tf32(L11.x));
        a1[0] = __float_as_uint(to_tf32(L00.y));
        a1[1] = __float_as_uint(to_tf32(L10.y));
        a1[2] = __float_as_uint(to_tf32(L01.y));
        a1[3] = __float_as_uint(to_tf32(L11.y));

        const int w0 = (k0 + tg)     * WPAD;
        const int w1 = (k0 + tg + 4) * WPAD;
#pragma unroll
        for (int nt = 0; nt < 6; nt++) {
            unsigned bfr[2];
            bfr[0] = wsu[w0 + 8 * nt + gid];    // (k=tg,   n=8nt+gid)  conflict-free
            bfr[1] = wsu[w1 + 8 * nt + gid];    // (k=tg+4, n=8nt+gid)
            mma_tf32(acc[0][nt], a0, bfr);
            mma_tf32(acc[1][nt], a1, bfr);
        }
    }

    // ================= epilogue =================
    // thread's channel pair per nt: Q = 4*nt + tg covers outputs (2Q, 2Q+1)
    float* outr = out + (long)NB * 6 * NPIX;
#pragma unroll
    for (int mt = 0; mt < 2; mt++) {
#pragma unroll
        for (int h = 0; h < 2; h++) {
            const int p = pbase + 2 * (h * 8 + gid) + mt;
#pragma unroll
            for (int nt = 0; nt < 6; nt++) {
                const float ve = acc[mt][nt][2 * h + 0];  // even channel (2Q)
                const float vo = acc[mt][nt][2 * h + 1];  // odd  channel (2Q+1)
                const int Q = 4 * nt + tg;
                if (Q < 3) {
                    // cls: out[(b*6 + o)*NPIX + p]
                    out[((long)b * 6 + 2 * Q + 0) * NPIX + p] = ve;
                    out[((long)b * 6 + 2 * Q + 1) * NPIX + p] = vo;
                } else {
                    // reg: (B, 3, 2, ny, nx, 7); even->y=0, odd->y=1
                    const int r  = Q - 3;
                    const int c3 = r / 7;
                    const int d  = r % 7;
                    outr[((((long)b * 3 + c3) * 2 + 0) * NPIX + p) * 7 + d] = ve;
                    outr[((((long)b * 3 + c3) * 2 + 1) * NPIX + p) * 7 + d] = vo;
                }
            }
        }
    }
}

extern "C" void kernel_launch(void* const* d_in, const int* in_sizes, int n_in,
                              void* d_out, int out_size)
{
    const float* feat = (const float*)d_in[0];
    const float* Wc   = (const float*)d_in[1];
    const float* bc   = (const float*)d_in[2];
    const float* Wr   = (const float*)d_in[3];
    const float* br   = (const float*)d_in[4];
    float* out = (float*)d_out;

    const int smem_bytes = (CIN * WPAD + NOUT) * (int)sizeof(float);  // 86208 B
    cudaFuncSetAttribute(proposal_kernel,
                         cudaFuncAttributeMaxDynamicSharedMemorySize, smem_bytes);

    const int threads = 256;                 // 8 warps x 32 pixels = 256 pixels/block
    const int blocks  = TOTAL_PIX / 256;     // 550, exact
    proposal_kernel<<<blocks, threads, smem_bytes>>>(feat, Wc, bc, Wr, br, out);
}

// round 8
// speedup vs baseline: 1.1590x; 1.1590x over previous
#include <cuda_runtime.h>

#define NOUT 48
#define WPAD 56          // ws row stride: tg*56 mod 32 = {0,24,16,8} -> conflict-free B LDS
#define CIN 384
#define NPIX 35200       // 200*176
#define NB 4
#define TOTAL_PIX 140800 // = 550 * 256

extern __shared__ float s_buf[];   // ws[CIN][WPAD] (tf32-rounded), then bs[48]

__device__ __forceinline__ float to_tf32(float x) {
    float r;
    asm("cvt.rna.tf32.f32 %0, %1;" : "=f"(r) : "f"(x));
    return r;
}

// D (=C in-place) 16x8 fp32 += A(16x8 tf32, row) * B(8x8 tf32, col)
__device__ __forceinline__ void mma_tf32(float c[4], const unsigned a[4], const unsigned b[2]) {
    asm("mma.sync.aligned.m16n8k8.row.col.f32.tf32.tf32.f32 "
        "{%0,%1,%2,%3}, {%4,%5,%6,%7}, {%8,%9}, {%0,%1,%2,%3};"
        : "+f"(c[0]), "+f"(c[1]), "+f"(c[2]), "+f"(c[3])
        : "r"(a[0]), "r"(a[1]), "r"(a[2]), "r"(a[3]), "r"(b[0]), "r"(b[1]));
}

__global__ __launch_bounds__(256, 2)
void proposal_kernel(const float* __restrict__ feat,
                     const float* __restrict__ Wc,
                     const float* __restrict__ bc,
                     const float* __restrict__ Wr,
                     const float* __restrict__ br,
                     float* __restrict__ out)
{
    float* ws = s_buf;                   // ws[c*WPAD + o] = tf32(W[o][c])
    float* bs = s_buf + CIN * WPAD;

    const int tid = threadIdx.x;

    for (int i = tid; i < CIN * NOUT; i += blockDim.x) {
        const int c = i / NOUT;
        const int o = i % NOUT;
        ws[c * WPAD + o] = to_tf32((o < 6) ? Wc[o * CIN + c] : Wr[(o - 6) * CIN + c]);
    }
    if (tid < NOUT) bs[tid] = (tid < 6) ? bc[tid] : br[tid - 6];
    __syncthreads();

    const int lane = tid & 31;
    const int warp = tid >> 5;          // 8 warps; warp owns 32 pixels
    const int gid  = lane >> 2;         // 0..7
    const int tg   = lane & 3;          // 0..3

    // R6 pixel mapping: fragment row = mt*16 + h*8 + gid
    const int m_base = blockIdx.x * 256 + warp * 32;
    int   rb[4];
    int   rp[4];
    const float* rptr[4];
#pragma unroll
    for (int i = 0; i < 4; i++) {
        const int mt = i >> 1, h = i & 1;
        const int g = m_base + mt * 16 + h * 8 + gid;
        rb[i] = g / NPIX;
        rp[i] = g % NPIX;
        rptr[i] = feat + (long)rb[i] * CIN * NPIX + rp[i];
    }

    // acc[mt][nt][0..3]: c0=(h0, even) c1=(h0, odd) c2=(h1, even) c3=(h1, odd)
    // columns: n = 8*nt + 2*tg (+1)
    float acc[2][6][4];
#pragma unroll
    for (int mt = 0; mt < 2; mt++)
#pragma unroll
        for (int nt = 0; nt < 6; nt++) {
            const float be = bs[8 * nt + 2 * tg];
            const float bo = bs[8 * nt + 2 * tg + 1];
            acc[mt][nt][0] = be; acc[mt][nt][1] = bo;
            acc[mt][nt][2] = be; acc[mt][nt][3] = bo;
        }

    const unsigned* wsu = (const unsigned*)ws;
    const long kstep0 = (long)tg * NPIX;
    const long kstep4 = (long)(tg + 4) * NPIX;

#pragma unroll 4
    for (int k0 = 0; k0 < CIN; k0 += 8) {
        const long kb = (long)k0 * NPIX;
        // 8 independent LDG.32 -> high MLP (R6-validated)
        unsigned a[2][4];
#pragma unroll
        for (int mt = 0; mt < 2; mt++) {
            a[mt][0] = __float_as_uint(to_tf32(rptr[2 * mt + 0][kb + kstep0]));
            a[mt][1] = __float_as_uint(to_tf32(rptr[2 * mt + 1][kb + kstep0]));
            a[mt][2] = __float_as_uint(to_tf32(rptr[2 * mt + 0][kb + kstep4]));
            a[mt][3] = __float_as_uint(to_tf32(rptr[2 * mt + 1][kb + kstep4]));
        }
        const int w0 = (k0 + tg)     * WPAD;   // conflict-free banks via WPAD=56
        const int w1 = (k0 + tg + 4) * WPAD;
#pragma unroll
        for (int nt = 0; nt < 6; nt++) {
            unsigned bfr[2];
            bfr[0] = wsu[w0 + 8 * nt + gid];
            bfr[1] = wsu[w1 + 8 * nt + gid];
            mma_tf32(acc[0][nt], a[0], bfr);
            mma_tf32(acc[1][nt], a[1], bfr);
        }
    }

    // ================= epilogue (R6-validated) =================
    // pair Q = 4*nt + tg covers outputs (2Q, 2Q+1); even->y0, odd->y1
    float* outr = out + (long)NB * 6 * NPIX;
#pragma unroll
    for (int mt = 0; mt < 2; mt++) {
#pragma unroll
        for (int h = 0; h < 2; h++) {
            const int i = 2 * mt + h;
            const int b = rb[i];
            const int p = rp[i];
#pragma unroll
            for (int nt = 0; nt < 6; nt++) {
                const float ve = acc[mt][nt][2 * h + 0];
                const float vo = acc[mt][nt][2 * h + 1];
                const int Q = 4 * nt + tg;
                if (Q < 3) {
                    out[((long)b * 6 + 2 * Q + 0) * NPIX + p] = ve;
                    out[((long)b * 6 + 2 * Q + 1) * NPIX + p] = vo;
                } else {
                    const int r  = Q - 3;
                    const int c3 = r / 7;
                    const int d  = r % 7;
                    outr[((((long)b * 3 + c3) * 2 + 0) * NPIX + p) * 7 + d] = ve;
                    outr[((((long)b * 3 + c3) * 2 + 1) * NPIX + p) * 7 + d] = vo;
                }
            }
        }
    }
}

extern "C" void kernel_launch(void* const* d_in, const int* in_sizes, int n_in,
                              void* d_out, int out_size)
{
    const float* feat = (const float*)d_in[0];
    const float* Wc   = (const float*)d_in[1];
    const float* bc   = (const float*)d_in[2];
    const float* Wr   = (const float*)d_in[3];
    const float* br   = (const float*)d_in[4];
    float* out = (float*)d_out;

    const int smem_bytes = (CIN * WPAD + NOUT) * (int)sizeof(float);  // 86208 B
    cudaFuncSetAttribute(proposal_kernel,
                         cudaFuncAttributeMaxDynamicSharedMemorySize, smem_bytes);

    const int threads = 256;                 // 8 warps x 32 pixels = 256 pixels/block
    const int blocks  = TOTAL_PIX / 256;     // 550, exact
    proposal_kernel<<<blocks, threads, smem_bytes>>>(feat, Wc, bc, Wr, br, out);
}

// round 11
// speedup vs baseline: 1.4927x; 1.2880x over previous
#include <cuda_runtime.h>

#define NOUT 48
#define CIN 384
#define NPIX 35200       // 200*176; %32==0, %8==0
#define NB 4
#define TOTAL_PIX 140800 // = 550 * 256
#define NSTAGE 48        // CIN / 8

#define WSTR 388         // ws2 row stride [o][k]: 388 mod 32 = 4 -> B-frag bank 4*gid+tg (CF)
#define WS_F (NOUT * WSTR)          // 18624
#define BS_OFF WS_F                 // bias at 18624
#define SA_OFF (WS_F + NOUT + 8)    // 18680 floats (*4 = 74720, 32B-aligned)
#define SA_ROW 264                  // 256 px + pad; 264 mod 32 = 8 -> A-frag CF
#define SA_BUF (8 * SA_ROW)         // 2112 floats per stage
#define SMEM_FLOATS (SA_OFF + 4 * SA_BUF)   // 27128 -> 108512 B

extern __shared__ float s_buf[];

__device__ __forceinline__ float to_tf32(float x) {
    float r;
    asm("cvt.rna.tf32.f32 %0, %1;" : "=f"(r) : "f"(x));
    return r;
}

__device__ __forceinline__ void mma_tf32(float c[4], const unsigned a[4], const unsigned b[2]) {
    asm("mma.sync.aligned.m16n8k8.row.col.f32.tf32.tf32.f32 "
        "{%0,%1,%2,%3}, {%4,%5,%6,%7}, {%8,%9}, {%0,%1,%2,%3};"
        : "+f"(c[0]), "+f"(c[1]), "+f"(c[2]), "+f"(c[3])
        : "r"(a[0]), "r"(a[1]), "r"(a[2]), "r"(a[3]), "r"(b[0]), "r"(b[1]));
}

__device__ __forceinline__ void cp16(unsigned sdst, const float* gsrc) {
    asm volatile("cp.async.cg.shared.global [%0], [%1], 16;\n"
                 :: "r"(sdst), "l"(gsrc) : "memory");
}
__device__ __forceinline__ void cp_commit() {
    asm volatile("cp.async.commit_group;\n" ::: "memory");
}
template <int N>
__device__ __forceinline__ void cp_wait() {
    asm volatile("cp.async.wait_group %0;\n" :: "n"(N) : "memory");
}

__global__ __launch_bounds__(256, 2)
void proposal_kernel(const float* __restrict__ feat,
                     const float* __restrict__ Wc,
                     const float* __restrict__ bc,
                     const float* __restrict__ Wr,
                     const float* __restrict__ br,
                     float* __restrict__ out)
{
    float* ws = s_buf;                   // ws[o*WSTR + k] = tf32(W[o][k])  (bounds: k<384<388 OK)
    float* bs = s_buf + BS_OFF;
    float* sa = s_buf + SA_OFF;          // 4-buffer A ring, block-wide

    const int tid  = threadIdx.x;
    const int lane = tid & 31;
    const int warp = tid >> 5;
    const int gid  = lane >> 2;          // 0..7
    const int tg   = lane & 3;           // 0..3

    // ---- per-thread cp.async role: channel c_l, 8-px chunk px0 (chunk never crosses batch) ----
    const int c_l = tid >> 5;            // 0..7
    const int px0 = (tid & 31) * 8;      // 0..248
    const int gp0 = blockIdx.x * 256 + px0;
    const int b0  = gp0 / NPIX;
    const int p0  = gp0 % NPIX;
    const float* gsrc = feat + (long)b0 * CIN * NPIX + (long)c_l * NPIX + p0;  // stage 0 src
    const unsigned sa_u = (unsigned)__cvta_generic_to_shared(sa);
    const unsigned dst_off = (unsigned)((c_l * SA_ROW + px0) * 4);             // within a buffer

    // ---- prologue: issue stages 0..2 (ring 4, prefetch distance 3) ----
#pragma unroll
    for (int s = 0; s < 3; s++) {
        const float* g = gsrc + (long)(8 * s) * NPIX;
        const unsigned d = sa_u + (unsigned)(s * SA_BUF * 4) + dst_off;
        cp16(d, g);
        cp16(d + 16, g + 4);
        cp_commit();
    }

    // ---- weight + bias staging ([o][k] layout) ----
    for (int i = tid; i < NOUT * CIN; i += blockDim.x) {
        const int o = i / CIN;
        const int k = i % CIN;
        ws[o * WSTR + k] = to_tf32((o < 6) ? Wc[o * CIN + k] : Wr[(o - 6) * CIN + k]);
    }
    if (tid < NOUT) bs[tid] = (tid < 6) ? bc[tid] : br[tid - 6];
    __syncthreads();

    // warp pixel window (32 px; never crosses batch since NPIX%32==0)
    const int wbase = blockIdx.x * 256 + warp * 32;
    const int bw    = wbase / NPIX;
    const int pw    = wbase % NPIX;
    const int mloc  = warp * 32;         // warp's local pixel base within block buffer

    // acc[mt][nt][0..3]: c0=(h0,even) c1=(h0,odd) c2=(h1,even) c3=(h1,odd); n=8*nt+2*tg(+1)
    float acc[2][6][4];
#pragma unroll
    for (int mt = 0; mt < 2; mt++)
#pragma unroll
        for (int nt = 0; nt < 6; nt++) {
            const float be = bs[8 * nt + 2 * tg];
            const float bo = bs[8 * nt + 2 * tg + 1];
            acc[mt][nt][0] = be; acc[mt][nt][1] = bo;
            acc[mt][nt][2] = be; acc[mt][nt][3] = bo;
        }

    const unsigned* wsu = (const unsigned*)ws;
    // A-fragment offsets within a stage buffer (bank = 8*tg + m, conflict-free)
    const int fr0 = tg * SA_ROW + mloc + gid;        // k=tg
    const int fr4 = (tg + 4) * SA_ROW + mloc + gid;  // k=tg+4
    // B rows for this thread: o = 8*nt + gid at k-column (k0+tg) / (k0+tg+4)
    const int wo = gid * WSTR;                        // + 8*nt*WSTR per nt

#define COMPUTE_STAGE(K0, BUF)                                                 \
    do {                                                                       \
        const float* sb = sa + (BUF) * SA_BUF;                                 \
        unsigned a0[4], a1[4];                                                 \
        a0[0] = __float_as_uint(to_tf32(sb[fr0 + 0]));                         \
        a0[1] = __float_as_uint(to_tf32(sb[fr0 + 8]));                         \
        a0[2] = __float_as_uint(to_tf32(sb[fr4 + 0]));                         \
        a0[3] = __float_as_uint(to_tf32(sb[fr4 + 8]));                         \
        a1[0] = __float_as_uint(to_tf32(sb[fr0 + 16]));                        \
        a1[1] = __float_as_uint(to_tf32(sb[fr0 + 24]));                        \
        a1[2] = __float_as_uint(to_tf32(sb[fr4 + 16]));                        \
        a1[3] = __float_as_uint(to_tf32(sb[fr4 + 24]));                        \
        _Pragma("unroll")                                                      \
        for (int nt = 0; nt < 6; nt++) {                                       \
            unsigned bfr[2];                                                   \
            bfr[0] = wsu[wo + nt * (8 * WSTR) + (K0) + tg];                    \
            bfr[1] = wsu[wo + nt * (8 * WSTR) + (K0) + tg + 4];                \
            mma_tf32(acc[0][nt], a0, bfr);                                     \
            mma_tf32(acc[1][nt], a1, bfr);                                     \
        }                                                                      \
    } while (0)

    // main loop: at sync(s) every warp has finished compute(s-1), so issuing
    // stage s+3 (buffer (s+3)&3, last read by stage s-1) after the sync is WAR-safe.
#pragma unroll 4
    for (int s = 0; s < NSTAGE - 3; s++) {
        cp_wait<2>();            // committed s+3 groups; <=2 pending => stage s ready
        __syncthreads();
        COMPUTE_STAGE(8 * s, s & 3);
        {
            const float* g = gsrc + (long)(8 * (s + 3)) * NPIX;
            const unsigned d = sa_u + (unsigned)(((s + 3) & 3) * SA_BUF * 4) + dst_off;
            cp16(d, g);
            cp16(d + 16, g + 4);
            cp_commit();
        }
    }
    // tail: stages 45, 46, 47 (all 48 groups committed; no more writes)
    cp_wait<2>();
    __syncthreads();
    COMPUTE_STAGE(8 * (NSTAGE - 3), (NSTAGE - 3) & 3);
    cp_wait<1>();
    __syncthreads();
    COMPUTE_STAGE(8 * (NSTAGE - 2), (NSTAGE - 2) & 3);
    cp_wait<0>();
    __syncthreads();
    COMPUTE_STAGE(8 * (NSTAGE - 1), (NSTAGE - 1) & 3);

    // ================= epilogue (R6/R8-validated) =================
    // pixel = pw + mt*16 + h*8 + gid; pair Q = 4*nt + tg -> outputs (2Q, 2Q+1); even->y0, odd->y1
    float* outr = out + (long)NB * 6 * NPIX;
#pragma unroll
    for (int mt = 0; mt < 2; mt++) {
#pragma unroll
        for (int h = 0; h < 2; h++) {
            const int p = pw + mt * 16 + h * 8 + gid;
#pragma unroll
            for (int nt = 0; nt < 6; nt++) {
                const float ve = acc[mt][nt][2 * h + 0];
                const float vo = acc[mt][nt][2 * h + 1];
                const int Q = 4 * nt + tg;
                if (Q < 3) {
                    out[((long)bw * 6 + 2 * Q + 0) * NPIX + p] = ve;
                    out[((long)bw * 6 + 2 * Q + 1) * NPIX + p] = vo;
                } else {
                    const int r  = Q - 3;
                    const int c3 = r / 7;
                    const int d  = r % 7;
                    outr[((((long)bw * 3 + c3) * 2 + 0) * NPIX + p) * 7 + d] = ve;
                    outr[((((long)bw * 3 + c3) * 2 + 1) * NPIX + p) * 7 + d] = vo;
                }
            }
        }
    }
#undef COMPUTE_STAGE
}

extern "C" void kernel_launch(void* const* d_in, const int* in_sizes, int n_in,
                              void* d_out, int out_size)
{
    const float* feat = (const float*)d_in[0];
    const float* Wc   = (const float*)d_in[1];
    const float* bc   = (const float*)d_in[2];
    const float* Wr   = (const float*)d_in[3];
    const float* br   = (const float*)d_in[4];
    float* out = (float*)d_out;

    const int smem_bytes = SMEM_FLOATS * (int)sizeof(float);   // 108512 B
    cudaFuncSetAttribute(proposal_kernel,
                         cudaFuncAttributeMaxDynamicSharedMemorySize, smem_bytes);

    const int threads = 256;                 // 8 warps x 32 px = 256 px/block
    const int blocks  = TOTAL_PIX / 256;     // 550, exact
    proposal_kernel<<<blocks, threads, smem_bytes>>>(feat, Wc, bc, Wr, br, out);
}